// round 2
// baseline (speedup 1.0000x reference)
#include <cuda_runtime.h>
#include <math_constants.h>

#define NB 4
#define NN 16384
#define NM 512
#define NC 128
#define NK 16
#define NL 6
#define NSTEPS 5

// ---------------- scratch (device globals: no allocations allowed) ----------
__device__ float g_feats[NB*NN*NC];            // encoder output
__device__ float g_Qf[NB*NN*NC];               // feats @ beta^T + b
__device__ float g_Gf[NB*NN*NC];               // feats @ gamma^T + b
__device__ float g_pos4[NB*NN*4];              // padded positions (x,y,z,0)
__device__ float g_wsel[NB*NM*NL*NC];          // selector walks
__device__ float g_rout[2][NB*NM*NL*NC];       // routed walks ping-pong
__device__ float g_disp[NB*NM*3];              // per-step displacements
__device__ int   g_idx[NB*NM];                 // current walk index

// ---------------- init: padded positions from xyz ---------------------------
__global__ void init_pos_kernel(const float* __restrict__ xyz) {
    int i = blockIdx.x * blockDim.x + threadIdx.x;
    if (i < NB*NN) {
        float x = xyz[i*3+0], y = xyz[i*3+1], z = xyz[i*3+2];
        float4 v = make_float4(x, y, z, 0.f);
        *(float4*)&g_pos4[(size_t)i*4] = v;
    }
}

// ---------------- encoder: feats = relu(xyz@W1^T+b1)@W2^T+b2 ---------------
__global__ void encode_kernel(const float* __restrict__ xyz,
                              const float* __restrict__ w1, const float* __restrict__ b1,
                              const float* __restrict__ w2, const float* __restrict__ b2) {
    __shared__ float h[4][64];
    int tid = threadIdx.x;              // 128 threads
    int p0 = blockIdx.x * 4;            // 4 points / block
    for (int i = tid; i < 4*64; i += 128) {
        int pt = i >> 6, j = i & 63;
        const float* x = xyz + (size_t)(p0 + pt) * 3;
        float v = b1[j] + w1[j*3+0]*x[0] + w1[j*3+1]*x[1] + w1[j*3+2]*x[2];
        h[pt][j] = fmaxf(v, 0.f);
    }
    __syncthreads();
    float acc[4];
    #pragma unroll
    for (int p = 0; p < 4; p++) acc[p] = b2[tid];
    const float4* wr = (const float4*)(w2 + (size_t)tid * 64);
    #pragma unroll
    for (int j4 = 0; j4 < 16; j4++) {
        float4 w = wr[j4];
        #pragma unroll
        for (int p = 0; p < 4; p++) {
            float4 hv = *(const float4*)&h[p][4*j4];
            acc[p] += w.x*hv.x + w.y*hv.y + w.z*hv.z + w.w*hv.w;
        }
    }
    #pragma unroll
    for (int p = 0; p < 4; p++)
        g_feats[(size_t)(p0 + p) * NC + tid] = acc[p];
}

// ---------------- beta/gamma projections (precomputed once) ----------------
__global__ void proj_kernel(const float* __restrict__ bw, const float* __restrict__ bb,
                            const float* __restrict__ gw, const float* __restrict__ gb) {
    __shared__ float sf[16][128];
    int c = threadIdx.x;                       // 128 threads
    size_t base = (size_t)blockIdx.x * 16 * 128;
    for (int i = c; i < 16*128; i += 128) sf[i>>7][i&127] = g_feats[base + i];
    __syncthreads();
    float accQ[16], accG[16];
    float biasQ = bb[c], biasG = gb[c];
    #pragma unroll
    for (int p = 0; p < 16; p++) { accQ[p] = biasQ; accG[p] = biasG; }
    const float4* wq = (const float4*)(bw + (size_t)c * 128);
    const float4* wg = (const float4*)(gw + (size_t)c * 128);
    for (int j4 = 0; j4 < 32; j4++) {
        float4 a = wq[j4];
        float4 g = wg[j4];
        #pragma unroll
        for (int p = 0; p < 16; p++) {
            float4 f = *(const float4*)&sf[p][4*j4];
            accQ[p] += a.x*f.x + a.y*f.y + a.z*f.z + a.w*f.w;
            accG[p] += g.x*f.x + g.y*f.y + g.z*f.z + g.w*f.w;
        }
    }
    #pragma unroll
    for (int p = 0; p < 16; p++) {
        g_Qf[base + (size_t)p*128 + c] = accQ[p];
        g_Gf[base + (size_t)p*128 + c] = accG[p];
    }
}

// ---------------- per-step walk init: idx=start, walk[0]=feats[start] ------
__global__ void walkinit_kernel(const int* __restrict__ start) {
    int gw = (blockIdx.x * blockDim.x + threadIdx.x) >> 5;
    int lane = threadIdx.x & 31;
    if (gw >= NB*NM) return;
    int s = start[gw];
    int b = gw >> 9;
    if (lane == 0) g_idx[gw] = s;
    const float* fr = g_feats + ((size_t)b*NN + s) * NC;
    float* wr = g_wsel + (size_t)gw * NL * NC;
    #pragma unroll
    for (int r = 0; r < 4; r++) wr[lane + 32*r] = fr[lane + 32*r];
}

// ---------------- fused KNN + gumbel-argmax step ---------------------------
// One warp per query. Warp-distributed sorted top-17 list (lanes 0..16 hold
// the sorted entries); O(1) parallel insert via ballot/popc/shfl_up, gated by
// tau = current 17th smallest distance.
__global__ void knn_kernel(const float* __restrict__ gumbel, int t, int l) {
    int gw = (blockIdx.x * blockDim.x + threadIdx.x) >> 5;
    int lane = threadIdx.x & 31;
    int wb = threadIdx.x >> 5;
    if (gw >= NB*NM) return;
    int b = gw >> 9, m = gw & 511;
    int qidx = g_idx[gw];
    const float4* pos = (const float4*)(g_pos4 + (size_t)b * NN * 4);
    float4 qp = pos[qidx];
    float qx = qp.x, qy = qp.y, qz = qp.z;

    float ld = CUDART_INF_F;     // list entry (lanes 0..16 meaningful)
    int   li = 0x7FFFFFFF;
    float tau = CUDART_INF_F;    // current 17th smallest, warp-uniform

    for (int i = lane; i < NN; i += 32) {
        float4 p = pos[i];
        float dx = p.x - qx, dy = p.y - qy, dz = p.z - qz;
        float d = dx*dx + dy*dy + dz*dz;
        unsigned bal = __ballot_sync(0xffffffffu, d < tau);
        while (bal) {
            int src = __ffs(bal) - 1; bal &= bal - 1;
            float dc = __shfl_sync(0xffffffffu, d, src);
            int   ic = __shfl_sync(0xffffffffu, i, src);
            unsigned lt = __ballot_sync(0xffffffffu, ld < dc) & 0x1FFFFu;
            int posn = __popc(lt);
            float pd = __shfl_up_sync(0xffffffffu, ld, 1);
            int   pi = __shfl_up_sync(0xffffffffu, li, 1);
            if (lane < 17) {
                if (lane == posn)      { ld = dc; li = ic; }
                else if (lane > posn)  { ld = pd; li = pi; }
            }
            tau = __shfl_sync(0xffffffffu, ld, 16);
        }
    }
    // lane 0 = self (d=0). knn = lanes 1..16 (ascending distance, like top_k).
    __shared__ int sknn[8][16];
    if (lane >= 1 && lane < 17) sknn[wb][lane - 1] = li;
    __syncwarp();

    // logits[k] = dot(Qf[qidx], Gf[knn[k]]) / sqrt(C), + gumbel, argmax
    const float* Q = g_Qf + ((size_t)b*NN + qidx) * NC;
    const float* G = g_Gf + (size_t)b*NN*NC;
    float qv[4];
    #pragma unroll
    for (int r = 0; r < 4; r++) qv[r] = Q[lane + 32*r];
    float pk[16];
    #pragma unroll
    for (int k = 0; k < 16; k++) {
        const float* gr = G + (size_t)sknn[wb][k] * NC;
        float s = 0.f;
        #pragma unroll
        for (int r = 0; r < 4; r++) s += qv[r] * gr[lane + 32*r];
        pk[k] = s;
    }
    #pragma unroll
    for (int k = 0; k < 16; k++) {
        #pragma unroll
        for (int off = 16; off; off >>= 1)
            pk[k] += __shfl_xor_sync(0xffffffffu, pk[k], off);
    }
    const float* gm = gumbel + ((((size_t)t*(NL-1) + l)*NB + b)*NM + m) * NK;
    float best = -CUDART_INF_F; int bk = 0;
    #pragma unroll
    for (int k = 0; k < 16; k++) {
        float s = pk[k] / 11.313708498984761f + gm[k];   // /sqrt(128)
        if (s > best) { best = s; bk = k; }
    }
    int nidx = sknn[wb][bk];
    if (lane == 0) g_idx[gw] = nidx;
    const float* fr = g_feats + ((size_t)b*NN + nidx) * NC;
    float* wr = g_wsel + ((size_t)gw * NL + (l + 1)) * NC;
    #pragma unroll
    for (int r = 0; r < 4; r++) wr[lane + 32*r] = fr[lane + 32*r];
}

// ---------------- route: tiny-L multihead attention + MLPs -----------------
__device__ __forceinline__ void mm128(const float (*in)[6][128],
                                      const float* __restrict__ W,
                                      const float* __restrict__ bias,
                                      float (*out)[6][128],
                                      int tid, bool doRelu) {
    float acc[12];
    float bv = bias[tid];
    #pragma unroll
    for (int i = 0; i < 12; i++) acc[i] = bv;
    const float4* wr = (const float4*)(W + (size_t)tid * 128);
    for (int j4 = 0; j4 < 32; j4++) {
        float4 w = __ldg(&wr[j4]);
        #pragma unroll
        for (int s = 0; s < 2; s++)
            #pragma unroll
            for (int l2 = 0; l2 < 6; l2++) {
                float4 x = *(const float4*)&in[s][l2][4*j4];
                acc[s*6+l2] += w.x*x.x + w.y*x.y + w.z*x.z + w.w*x.w;
            }
    }
    #pragma unroll
    for (int s = 0; s < 2; s++)
        #pragma unroll
        for (int l2 = 0; l2 < 6; l2++) {
            float v = acc[s*6+l2];
            out[s][l2][tid] = doRelu ? fmaxf(v, 0.f) : v;
        }
}

__global__ void route_kernel(const float* __restrict__ w_in, const float* __restrict__ b_in,
                             const float* __restrict__ w_out, const float* __restrict__ b_out,
                             const float* __restrict__ rt_w1, const float* __restrict__ rt_b1,
                             const float* __restrict__ rt_w2, const float* __restrict__ rt_b2,
                             int curBuf, int prevBuf) {
    __shared__ float xin[2][6][128];  // curr, later reused as attn output
    __shared__ float pin[2][6][128];  // prev, later reused as o1
    __shared__ float qs[2][6][128];   // q, later reused as r1
    __shared__ float ks[2][6][128];   // k, later reused as final
    __shared__ float vs[2][6][128];
    __shared__ float sc[2][4][6][6];
    int tid = threadIdx.x;
    size_t seq0 = (size_t)blockIdx.x * 2;
    const float* curr = g_wsel;
    const float* prev = (prevBuf < 0) ? g_wsel : g_rout[prevBuf];
    for (int i = tid; i < 2*6*128; i += 128) {
        ((float*)xin)[i] = curr[seq0*6*128 + i];
        ((float*)pin)[i] = prev[seq0*6*128 + i];
    }
    __syncthreads();
    mm128(xin, w_in,            b_in,        qs, tid, false);   // wq rows 0..127
    mm128(pin, w_in + 128*128,  b_in + 128,  ks, tid, false);   // wk
    mm128(pin, w_in + 256*128,  b_in + 256,  vs, tid, false);   // wv
    __syncthreads();
    // attention: 8 (s,h) pairs, one warp per pair (x2 sequentially)
    int warp = tid >> 5, lane = tid & 31;
    for (int pp = warp; pp < 8; pp += 4) {
        int s = pp >> 2, h = pp & 3;
        for (int e = lane; e < 36; e += 32) {
            int lq = e / 6, lk = e % 6;
            const float* qrow = &qs[s][lq][h*32];
            const float* krow = &ks[s][lk][h*32];
            float d = 0.f;
            #pragma unroll
            for (int dd = 0; dd < 32; dd++) d += qrow[dd] * krow[dd];
            sc[s][h][lq][lk] = d / 5.656854249492381f;   // /sqrt(32)
        }
        __syncwarp();
        if (lane < 6) {
            float mx = -CUDART_INF_F;
            #pragma unroll
            for (int j = 0; j < 6; j++) mx = fmaxf(mx, sc[s][h][lane][j]);
            float ex[6]; float sum = 0.f;
            #pragma unroll
            for (int j = 0; j < 6; j++) { ex[j] = expf(sc[s][h][lane][j] - mx); sum += ex[j]; }
            #pragma unroll
            for (int j = 0; j < 6; j++) sc[s][h][lane][j] = ex[j] / sum;
        }
        __syncwarp();
        for (int lq = 0; lq < 6; lq++) {
            float o = 0.f;
            #pragma unroll
            for (int j = 0; j < 6; j++) o += sc[s][h][lq][j] * vs[s][j][h*32 + lane];
            xin[s][lq][h*32 + lane] = o;   // attn out -> xin (curr no longer needed)
        }
    }
    __syncthreads();
    mm128(xin, w_out, b_out, pin, tid, false);   // o1
    __syncthreads();
    mm128(pin, rt_w1, rt_b1, qs, tid, true);     // r1 = relu
    __syncthreads();
    mm128(qs, rt_w2, rt_b2, ks, tid, false);     // final
    __syncthreads();
    float* dst = g_rout[curBuf] + seq0*6*128;
    for (int i = tid; i < 2*6*128; i += 128) dst[i] = ((float*)ks)[i];
}

// ---------------- predict: disp = tanh(relu(x@W1^T+b1)@W2^T+b2) ------------
__global__ void predict_kernel(const float* __restrict__ pw1, const float* __restrict__ pb1,
                               const float* __restrict__ pw2, const float* __restrict__ pb2,
                               int curBuf) {
    __shared__ float x[256];
    __shared__ float h[64];
    int w = blockIdx.x;                // (b,m)
    int tid = threadIdx.x;             // 64 threads
    const float* wk = g_rout[curBuf] + (size_t)w * NL * NC;
    for (int c = tid; c < 128; c += 64) {
        float cent = wk[c];
        float s = 0.f;
        #pragma unroll
        for (int l2 = 1; l2 < 6; l2++) s += (wk[l2*128 + c] - cent);
        x[c] = s * (1.0f / 5.0f);
        x[128 + c] = cent;
    }
    __syncthreads();
    {
        float acc = pb1[tid];
        const float4* wr = (const float4*)(pw1 + (size_t)tid * 256);
        #pragma unroll 8
        for (int j4 = 0; j4 < 64; j4++) {
            float4 wv = wr[j4];
            float4 xv = *(const float4*)&x[4*j4];
            acc += wv.x*xv.x + wv.y*xv.y + wv.z*xv.z + wv.w*xv.w;
        }
        h[tid] = fmaxf(acc, 0.f);
    }
    __syncthreads();
    if (tid < 3) {
        float acc = pb2[tid];
        const float* wr = pw2 + tid * 64;
        #pragma unroll 8
        for (int j = 0; j < 64; j++) acc += wr[j] * h[j];
        g_disp[(size_t)w * 3 + tid] = tanhf(acc);
    }
}

// ---------------- deterministic duplicate-aware scatter-add ----------------
__global__ void scatter_kernel(const int* __restrict__ start) {
    int gid = blockIdx.x * blockDim.x + threadIdx.x;
    if (gid >= NB*NM) return;
    int b = gid >> 9, m = gid & 511;
    int n = start[gid];
    const int* sb = start + b * NM;
    for (int j = 0; j < m; j++) if (sb[j] == n) return;   // not the first owner
    float sx = 0.f, sy = 0.f, sz = 0.f;
    for (int j = m; j < NM; j++) {
        if (sb[j] == n) {
            const float* d = g_disp + (size_t)(b*NM + j) * 3;
            sx += d[0]; sy += d[1]; sz += d[2];
        }
    }
    float* p = g_pos4 + ((size_t)b*NN + n) * 4;
    p[0] += sx; p[1] += sy; p[2] += sz;
}

// ---------------- finalize: padded positions -> output ---------------------
__global__ void finalize_kernel(float* __restrict__ out) {
    int i = blockIdx.x * blockDim.x + threadIdx.x;
    if (i < NB*NN) {
        out[i*3+0] = g_pos4[(size_t)i*4+0];
        out[i*3+1] = g_pos4[(size_t)i*4+1];
        out[i*3+2] = g_pos4[(size_t)i*4+2];
    }
}

// ---------------- host driver ----------------------------------------------
extern "C" void kernel_launch(void* const* d_in, const int* in_sizes, int n_in,
                              void* d_out, int out_size) {
    (void)in_sizes; (void)n_in; (void)out_size;
    const float* xyz      = (const float*)d_in[0];
    const int*   start    = (const int*)  d_in[1];
    const float* gumbel   = (const float*)d_in[2];
    const float* enc_w1   = (const float*)d_in[3];
    const float* enc_b1   = (const float*)d_in[4];
    const float* enc_w2   = (const float*)d_in[5];
    const float* enc_b2   = (const float*)d_in[6];
    const float* beta_w   = (const float*)d_in[7];
    const float* beta_b   = (const float*)d_in[8];
    const float* gamma_w  = (const float*)d_in[9];
    const float* gamma_b  = (const float*)d_in[10];
    const float* attn_w_in  = (const float*)d_in[11];
    const float* attn_b_in  = (const float*)d_in[12];
    const float* attn_w_out = (const float*)d_in[13];
    const float* attn_b_out = (const float*)d_in[14];
    const float* rt_w1    = (const float*)d_in[15];
    const float* rt_b1    = (const float*)d_in[16];
    const float* rt_w2    = (const float*)d_in[17];
    const float* rt_b2    = (const float*)d_in[18];
    const float* pred_w1  = (const float*)d_in[19];
    const float* pred_b1  = (const float*)d_in[20];
    const float* pred_w2  = (const float*)d_in[21];
    const float* pred_b2  = (const float*)d_in[22];

    init_pos_kernel<<<(NB*NN + 127)/128, 128>>>(xyz);
    encode_kernel<<<NB*NN/4, 128>>>(xyz, enc_w1, enc_b1, enc_w2, enc_b2);
    proj_kernel<<<NB*NN/16, 128>>>(beta_w, beta_b, gamma_w, gamma_b);

    for (int t = 0; t < NSTEPS; t++) {
        int cur = t & 1;
        int prv = (t == 0) ? -1 : (1 - cur);
        walkinit_kernel<<<NB*NM/8, 256>>>(start);
        for (int l = 0; l < NL - 1; l++)
            knn_kernel<<<NB*NM/8, 256>>>(gumbel, t, l);
        route_kernel<<<NB*NM/2, 128>>>(attn_w_in, attn_b_in, attn_w_out, attn_b_out,
                                       rt_w1, rt_b1, rt_w2, rt_b2, cur, prv);
        predict_kernel<<<NB*NM, 64>>>(pred_w1, pred_b1, pred_w2, pred_b2, cur);
        scatter_kernel<<<(NB*NM + 127)/128, 128>>>(start);
    }
    finalize_kernel<<<(NB*NN + 127)/128, 128>>>((float*)d_out);
}

// round 3
// speedup vs baseline: 1.0446x; 1.0446x over previous
#include <cuda_runtime.h>
#include <math_constants.h>

#define NB 4
#define NN 16384
#define NM 512
#define NC 128
#define NK 16
#define NL 6
#define NSTEPS 5

// ---------------- scratch (device globals: no allocations allowed) ----------
__device__ float g_feats[NB*NN*NC];            // encoder output
__device__ float g_Qf[NB*NN*NC];               // feats @ beta^T + b
__device__ float g_Gf[NB*NN*NC];               // feats @ gamma^T + b
__device__ float g_pos4[NB*NN*4];              // padded positions (x,y,z,0)
__device__ float g_wsel[NB*NM*NL*NC];          // selector walks
__device__ float g_rout[2][NB*NM*NL*NC];       // routed walks ping-pong
__device__ float g_disp[NB*NM*3];              // per-step displacements
__device__ int   g_idx[NB*NM];                 // current walk index

// ---------------- f32x2 packed helpers --------------------------------------
__device__ __forceinline__ void dfma2(unsigned long long& d,
                                      unsigned long long a,
                                      unsigned long long b) {
    asm("fma.rn.f32x2 %0, %1, %2, %0;" : "+l"(d) : "l"(a), "l"(b));
}
__device__ __forceinline__ unsigned long long packdup(float w) {
    unsigned long long r;
    asm("mov.b64 %0, {%1, %1};" : "=l"(r) : "f"(w));
    return r;
}
__device__ __forceinline__ void unpack2(unsigned long long a, float& lo, float& hi) {
    asm("mov.b64 {%0, %1}, %2;" : "=f"(lo), "=f"(hi) : "l"(a));
}

// ---------------- init: padded positions from xyz ---------------------------
__global__ void init_pos_kernel(const float* __restrict__ xyz) {
    int i = blockIdx.x * blockDim.x + threadIdx.x;
    if (i < NB*NN) {
        float x = xyz[i*3+0], y = xyz[i*3+1], z = xyz[i*3+2];
        float4 v = make_float4(x, y, z, 0.f);
        *(float4*)&g_pos4[(size_t)i*4] = v;
    }
}

// ---------------- encoder: feats = relu(xyz@W1^T+b1)@W2^T+b2 ---------------
__global__ void encode_kernel(const float* __restrict__ xyz,
                              const float* __restrict__ w1, const float* __restrict__ b1,
                              const float* __restrict__ w2, const float* __restrict__ b2) {
    __shared__ float h[4][64];
    int tid = threadIdx.x;              // 128 threads
    int p0 = blockIdx.x * 4;            // 4 points / block
    for (int i = tid; i < 4*64; i += 128) {
        int pt = i >> 6, j = i & 63;
        const float* x = xyz + (size_t)(p0 + pt) * 3;
        float v = b1[j] + w1[j*3+0]*x[0] + w1[j*3+1]*x[1] + w1[j*3+2]*x[2];
        h[pt][j] = fmaxf(v, 0.f);
    }
    __syncthreads();
    float acc[4];
    #pragma unroll
    for (int p = 0; p < 4; p++) acc[p] = b2[tid];
    const float4* wr = (const float4*)(w2 + (size_t)tid * 64);
    #pragma unroll
    for (int j4 = 0; j4 < 16; j4++) {
        float4 w = wr[j4];
        #pragma unroll
        for (int p = 0; p < 4; p++) {
            float4 hv = *(const float4*)&h[p][4*j4];
            acc[p] += w.x*hv.x + w.y*hv.y + w.z*hv.z + w.w*hv.w;
        }
    }
    #pragma unroll
    for (int p = 0; p < 4; p++)
        g_feats[(size_t)(p0 + p) * NC + tid] = acc[p];
}

// ---------------- beta/gamma projections (precomputed once) ----------------
__global__ void proj_kernel(const float* __restrict__ bw, const float* __restrict__ bb,
                            const float* __restrict__ gw, const float* __restrict__ gb) {
    __shared__ float sf[16][128];
    int c = threadIdx.x;                       // 128 threads
    size_t base = (size_t)blockIdx.x * 16 * 128;
    for (int i = c; i < 16*128; i += 128) sf[i>>7][i&127] = g_feats[base + i];
    __syncthreads();
    float accQ[16], accG[16];
    float biasQ = bb[c], biasG = gb[c];
    #pragma unroll
    for (int p = 0; p < 16; p++) { accQ[p] = biasQ; accG[p] = biasG; }
    const float4* wq = (const float4*)(bw + (size_t)c * 128);
    const float4* wg = (const float4*)(gw + (size_t)c * 128);
    for (int j4 = 0; j4 < 32; j4++) {
        float4 a = wq[j4];
        float4 g = wg[j4];
        #pragma unroll
        for (int p = 0; p < 16; p++) {
            float4 f = *(const float4*)&sf[p][4*j4];
            accQ[p] += a.x*f.x + a.y*f.y + a.z*f.z + a.w*f.w;
            accG[p] += g.x*f.x + g.y*f.y + g.z*f.z + g.w*f.w;
        }
    }
    #pragma unroll
    for (int p = 0; p < 16; p++) {
        g_Qf[base + (size_t)p*128 + c] = accQ[p];
        g_Gf[base + (size_t)p*128 + c] = accG[p];
    }
}

// ---------------- per-step walk init: idx=start, walk[0]=feats[start] ------
__global__ void walkinit_kernel(const int* __restrict__ start) {
    int gw = (blockIdx.x * blockDim.x + threadIdx.x) >> 5;
    int lane = threadIdx.x & 31;
    if (gw >= NB*NM) return;
    int s = start[gw];
    int b = gw >> 9;
    if (lane == 0) g_idx[gw] = s;
    const float* fr = g_feats + ((size_t)b*NN + s) * NC;
    float* wr = g_wsel + (size_t)gw * NL * NC;
    #pragma unroll
    for (int r = 0; r < 4; r++) wr[lane + 32*r] = fr[lane + 32*r];
}

// ---------------- fused KNN + gumbel-argmax step ---------------------------
// 128 blocks x 256 threads. Each block owns 16 queries of one batch and
// streams the batch's 16384 candidate positions through 32KB smem tiles.
// Each warp scans every tile for TWO queries, maintaining two
// warp-distributed sorted top-17 lists (lanes 0..16); O(1) parallel insert
// via ballot/popc/shfl_up gated by tau = current 17th smallest distance.
#define KQPB 16
#define KTPB 256
#define KTILE 2048

__device__ __forceinline__ void knn_insert(unsigned bal, float d, int ci,
                                           float& ld, int& li, float& tau, int lane) {
    while (bal) {
        int src = __ffs(bal) - 1; bal &= bal - 1;
        float dc = __shfl_sync(0xffffffffu, d, src);
        int   ic = __shfl_sync(0xffffffffu, ci, src);
        unsigned lt = __ballot_sync(0xffffffffu,
                                    (ld < dc) || ((ld == dc) && (li < ic))) & 0x1FFFFu;
        int pn = __popc(lt);
        float pd = __shfl_up_sync(0xffffffffu, ld, 1);
        int   pi = __shfl_up_sync(0xffffffffu, li, 1);
        if (lane < 17) {
            if (lane == pn)      { ld = dc; li = ic; }
            else if (lane > pn)  { ld = pd; li = pi; }
        }
        tau = __shfl_sync(0xffffffffu, ld, 16);
    }
}

__device__ __forceinline__ void knn_finish(int b, int m, int qi, const int* knnrow,
                                           const float* __restrict__ gumbel,
                                           int t, int l, int lane) {
    const float* Q = g_Qf + ((size_t)b*NN + qi) * NC;
    const float* G = g_Gf + (size_t)b*NN*NC;
    float qv0 = Q[lane], qv1 = Q[lane+32], qv2 = Q[lane+64], qv3 = Q[lane+96];
    float pk[16];
    #pragma unroll
    for (int k = 0; k < 16; k++) {
        const float* gr = G + (size_t)knnrow[k] * NC;
        pk[k] = qv0*gr[lane] + qv1*gr[lane+32] + qv2*gr[lane+64] + qv3*gr[lane+96];
    }
    #pragma unroll
    for (int k = 0; k < 16; k++) {
        #pragma unroll
        for (int off = 16; off; off >>= 1)
            pk[k] += __shfl_xor_sync(0xffffffffu, pk[k], off);
    }
    const float* gm = gumbel + ((((size_t)t*(NL-1) + l)*NB + b)*NM + m) * NK;
    float best = -CUDART_INF_F; int bk = 0;
    #pragma unroll
    for (int k = 0; k < 16; k++) {
        float s = pk[k] / 11.313708498984761f + gm[k];   // /sqrt(128)
        if (s > best) { best = s; bk = k; }
    }
    int nidx = knnrow[bk];
    int gw = b*NM + m;
    if (lane == 0) g_idx[gw] = nidx;
    const float* fr = g_feats + ((size_t)b*NN + nidx) * NC;
    float* wr = g_wsel + ((size_t)gw * NL + (l + 1)) * NC;
    #pragma unroll
    for (int r = 0; r < 4; r++) wr[lane + 32*r] = fr[lane + 32*r];
}

__global__ void knn_kernel(const float* __restrict__ gumbel, int t, int l) {
    __shared__ float4 stile[KTILE];
    __shared__ int sknn[KQPB][NK];
    const int bpb = NM / KQPB;                 // 32 blocks per batch
    int b  = blockIdx.x / bpb;
    int m0 = (blockIdx.x % bpb) * KQPB;
    int warp = threadIdx.x >> 5, lane = threadIdx.x & 31;
    int mA = m0 + warp*2, mB = mA + 1;
    int qiA = g_idx[b*NM + mA], qiB = g_idx[b*NM + mB];
    const float4* pos = (const float4*)(g_pos4 + (size_t)b * NN * 4);
    float4 qa = pos[qiA], qb = pos[qiB];

    float ldA = CUDART_INF_F, ldB = CUDART_INF_F;
    int   liA = 0x7FFFFFFF,   liB = 0x7FFFFFFF;
    float tauA = CUDART_INF_F, tauB = CUDART_INF_F;

    for (int tb = 0; tb < NN/KTILE; tb++) {
        __syncthreads();
        const float4* src = pos + tb*KTILE;
        for (int i = threadIdx.x; i < KTILE; i += KTPB) stile[i] = src[i];
        __syncthreads();
        int base = tb * KTILE;
        for (int j = lane; j < KTILE; j += 32) {
            float4 p = stile[j];
            int ci = base + j;
            float dxa = p.x - qa.x, dya = p.y - qa.y, dza = p.z - qa.z;
            float dA = dxa*dxa + dya*dya + dza*dza;
            float dxb = p.x - qb.x, dyb = p.y - qb.y, dzb = p.z - qb.z;
            float dB = dxb*dxb + dyb*dyb + dzb*dzb;
            unsigned balA = __ballot_sync(0xffffffffu, dA < tauA);
            if (balA) knn_insert(balA, dA, ci, ldA, liA, tauA, lane);
            unsigned balB = __ballot_sync(0xffffffffu, dB < tauB);
            if (balB) knn_insert(balB, dB, ci, ldB, liB, tauB, lane);
        }
    }
    // lane 0 = self (d=0). knn = lanes 1..16 ascending (d, idx) like top_k.
    if (lane >= 1 && lane < 17) {
        sknn[warp*2 + 0][lane - 1] = liA;
        sknn[warp*2 + 1][lane - 1] = liB;
    }
    __syncwarp();
    knn_finish(b, mA, qiA, sknn[warp*2 + 0], gumbel, t, l, lane);
    knn_finish(b, mB, qiB, sknn[warp*2 + 1], gumbel, t, l, lane);
}

// ---------------- route: tiny-L multihead attention + MLPs -----------------
// Stage buffers hold TWO sequences interleaved: buf[l][channel][s], so each
// 64-bit shared load yields a ready-packed f32x2 operand pair and the matmul
// inner loop runs on fma.rn.f32x2 (half the fma-pipe work of scalar FFMA).
__device__ __forceinline__ void mm128i(const float (*in)[128][2],
                                       const float* __restrict__ W,
                                       const float* __restrict__ bias,
                                       float (*out)[128][2],
                                       int tid, bool doRelu) {
    unsigned long long acc[6];
    unsigned long long bb = packdup(bias[tid]);
    #pragma unroll
    for (int i = 0; i < 6; i++) acc[i] = bb;
    const float4* wr = (const float4*)(W + (size_t)tid * 128);
    const unsigned long long* inu = (const unsigned long long*)in;
    for (int j4 = 0; j4 < 32; j4++) {
        float4 w = __ldg(&wr[j4]);
        unsigned long long w0 = packdup(w.x), w1 = packdup(w.y);
        unsigned long long w2 = packdup(w.z), w3 = packdup(w.w);
        #pragma unroll
        for (int l2 = 0; l2 < 6; l2++) {
            const unsigned long long* row = inu + l2*128 + 4*j4;
            dfma2(acc[l2], row[0], w0);
            dfma2(acc[l2], row[1], w1);
            dfma2(acc[l2], row[2], w2);
            dfma2(acc[l2], row[3], w3);
        }
    }
    #pragma unroll
    for (int l2 = 0; l2 < 6; l2++) {
        float v0, v1;
        unpack2(acc[l2], v0, v1);
        if (doRelu) { v0 = fmaxf(v0, 0.f); v1 = fmaxf(v1, 0.f); }
        out[l2][tid][0] = v0;
        out[l2][tid][1] = v1;
    }
}

__global__ void route_kernel(const float* __restrict__ w_in, const float* __restrict__ b_in,
                             const float* __restrict__ w_out, const float* __restrict__ b_out,
                             const float* __restrict__ rt_w1, const float* __restrict__ rt_b1,
                             const float* __restrict__ rt_w2, const float* __restrict__ rt_b2,
                             int curBuf, int prevBuf) {
    __shared__ __align__(16) float xin[6][128][2];  // curr, reused as attn out
    __shared__ __align__(16) float pin[6][128][2];  // prev, reused as o1
    __shared__ __align__(16) float qs[6][128][2];   // q, reused as r1
    __shared__ __align__(16) float ks[6][128][2];   // k, reused as final
    __shared__ __align__(16) float vs[6][128][2];
    __shared__ float sc[2][4][6][6];
    int tid = threadIdx.x;
    size_t seq0 = (size_t)blockIdx.x * 2;
    const float* curr = g_wsel;
    const float* prev = (prevBuf < 0) ? g_wsel : g_rout[prevBuf];
    for (int i = tid; i < 2*6*128; i += 128) {
        int s = i / 768, r = i % 768;          // r = l*128 + c
        ((float*)xin)[r*2 + s] = curr[(seq0 + s)*768 + r];
        ((float*)pin)[r*2 + s] = prev[(seq0 + s)*768 + r];
    }
    __syncthreads();
    mm128i(xin, w_in,            b_in,        qs, tid, false);   // wq
    mm128i(pin, w_in + 128*128,  b_in + 128,  ks, tid, false);   // wk
    mm128i(pin, w_in + 256*128,  b_in + 256,  vs, tid, false);   // wv
    __syncthreads();
    // attention: 8 (s,h) pairs, one warp per pair (x2 sequentially)
    int warp = tid >> 5, lane = tid & 31;
    for (int pp = warp; pp < 8; pp += 4) {
        int s = pp >> 2, h = pp & 3;
        for (int e = lane; e < 36; e += 32) {
            int lq = e / 6, lk = e % 6;
            float d = 0.f;
            #pragma unroll
            for (int dd = 0; dd < 32; dd++)
                d += qs[lq][h*32 + dd][s] * ks[lk][h*32 + dd][s];
            sc[s][h][lq][lk] = d / 5.656854249492381f;   // /sqrt(32)
        }
        __syncwarp();
        if (lane < 6) {
            float mx = -CUDART_INF_F;
            #pragma unroll
            for (int j = 0; j < 6; j++) mx = fmaxf(mx, sc[s][h][lane][j]);
            float ex[6]; float sum = 0.f;
            #pragma unroll
            for (int j = 0; j < 6; j++) { ex[j] = expf(sc[s][h][lane][j] - mx); sum += ex[j]; }
            #pragma unroll
            for (int j = 0; j < 6; j++) sc[s][h][lane][j] = ex[j] / sum;
        }
        __syncwarp();
        for (int lq = 0; lq < 6; lq++) {
            float o = 0.f;
            #pragma unroll
            for (int j = 0; j < 6; j++) o += sc[s][h][lq][j] * vs[j][h*32 + lane][s];
            xin[lq][h*32 + lane][s] = o;   // attn out -> xin
        }
    }
    __syncthreads();
    mm128i(xin, w_out, b_out, pin, tid, false);   // o1
    __syncthreads();
    mm128i(pin, rt_w1, rt_b1, qs, tid, true);     // r1 = relu
    __syncthreads();
    mm128i(qs, rt_w2, rt_b2, ks, tid, false);     // final
    __syncthreads();
    float* dst = g_rout[curBuf] + seq0*768;
    for (int i = tid; i < 2*6*128; i += 128) {
        int s = i / 768, r = i % 768;
        dst[(size_t)s*768 + r] = ((float*)ks)[r*2 + s];
    }
}

// ---------------- predict: disp = tanh(relu(x@W1^T+b1)@W2^T+b2) ------------
__global__ void predict_kernel(const float* __restrict__ pw1, const float* __restrict__ pb1,
                               const float* __restrict__ pw2, const float* __restrict__ pb2,
                               int curBuf) {
    __shared__ float x[256];
    __shared__ float h[64];
    int w = blockIdx.x;                // (b,m)
    int tid = threadIdx.x;             // 64 threads
    const float* wk = g_rout[curBuf] + (size_t)w * NL * NC;
    for (int c = tid; c < 128; c += 64) {
        float cent = wk[c];
        float s = 0.f;
        #pragma unroll
        for (int l2 = 1; l2 < 6; l2++) s += (wk[l2*128 + c] - cent);
        x[c] = s * (1.0f / 5.0f);
        x[128 + c] = cent;
    }
    __syncthreads();
    {
        float acc = pb1[tid];
        const float4* wr = (const float4*)(pw1 + (size_t)tid * 256);
        #pragma unroll 8
        for (int j4 = 0; j4 < 64; j4++) {
            float4 wv = wr[j4];
            float4 xv = *(const float4*)&x[4*j4];
            acc += wv.x*xv.x + wv.y*xv.y + wv.z*xv.z + wv.w*xv.w;
        }
        h[tid] = fmaxf(acc, 0.f);
    }
    __syncthreads();
    if (tid < 3) {
        float acc = pb2[tid];
        const float* wr = pw2 + tid * 64;
        #pragma unroll 8
        for (int j = 0; j < 64; j++) acc += wr[j] * h[j];
        g_disp[(size_t)w * 3 + tid] = tanhf(acc);
    }
}

// ---------------- deterministic duplicate-aware scatter-add ----------------
__global__ void scatter_kernel(const int* __restrict__ start) {
    int gid = blockIdx.x * blockDim.x + threadIdx.x;
    if (gid >= NB*NM) return;
    int b = gid >> 9, m = gid & 511;
    int n = start[gid];
    const int* sb = start + b * NM;
    for (int j = 0; j < m; j++) if (sb[j] == n) return;   // not the first owner
    float sx = 0.f, sy = 0.f, sz = 0.f;
    for (int j = m; j < NM; j++) {
        if (sb[j] == n) {
            const float* d = g_disp + (size_t)(b*NM + j) * 3;
            sx += d[0]; sy += d[1]; sz += d[2];
        }
    }
    float* p = g_pos4 + ((size_t)b*NN + n) * 4;
    p[0] += sx; p[1] += sy; p[2] += sz;
}

// ---------------- finalize: padded positions -> output ---------------------
__global__ void finalize_kernel(float* __restrict__ out) {
    int i = blockIdx.x * blockDim.x + threadIdx.x;
    if (i < NB*NN) {
        out[i*3+0] = g_pos4[(size_t)i*4+0];
        out[i*3+1] = g_pos4[(size_t)i*4+1];
        out[i*3+2] = g_pos4[(size_t)i*4+2];
    }
}

// ---------------- host driver ----------------------------------------------
extern "C" void kernel_launch(void* const* d_in, const int* in_sizes, int n_in,
                              void* d_out, int out_size) {
    (void)in_sizes; (void)n_in; (void)out_size;
    const float* xyz      = (const float*)d_in[0];
    const int*   start    = (const int*)  d_in[1];
    const float* gumbel   = (const float*)d_in[2];
    const float* enc_w1   = (const float*)d_in[3];
    const float* enc_b1   = (const float*)d_in[4];
    const float* enc_w2   = (const float*)d_in[5];
    const float* enc_b2   = (const float*)d_in[6];
    const float* beta_w   = (const float*)d_in[7];
    const float* beta_b   = (const float*)d_in[8];
    const float* gamma_w  = (const float*)d_in[9];
    const float* gamma_b  = (const float*)d_in[10];
    const float* attn_w_in  = (const float*)d_in[11];
    const float* attn_b_in  = (const float*)d_in[12];
    const float* attn_w_out = (const float*)d_in[13];
    const float* attn_b_out = (const float*)d_in[14];
    const float* rt_w1    = (const float*)d_in[15];
    const float* rt_b1    = (const float*)d_in[16];
    const float* rt_w2    = (const float*)d_in[17];
    const float* rt_b2    = (const float*)d_in[18];
    const float* pred_w1  = (const float*)d_in[19];
    const float* pred_b1  = (const float*)d_in[20];
    const float* pred_w2  = (const float*)d_in[21];
    const float* pred_b2  = (const float*)d_in[22];

    init_pos_kernel<<<(NB*NN + 127)/128, 128>>>(xyz);
    encode_kernel<<<NB*NN/4, 128>>>(xyz, enc_w1, enc_b1, enc_w2, enc_b2);
    proj_kernel<<<NB*NN/16, 128>>>(beta_w, beta_b, gamma_w, gamma_b);

    for (int t = 0; t < NSTEPS; t++) {
        int cur = t & 1;
        int prv = (t == 0) ? -1 : (1 - cur);
        walkinit_kernel<<<NB*NM/8, 256>>>(start);
        for (int l = 0; l < NL - 1; l++)
            knn_kernel<<<NB*NM/KQPB, KTPB>>>(gumbel, t, l);
        route_kernel<<<NB*NM/2, 128>>>(attn_w_in, attn_b_in, attn_w_out, attn_b_out,
                                       rt_w1, rt_b1, rt_w2, rt_b2, cur, prv);
        predict_kernel<<<NB*NM, 64>>>(pred_w1, pred_b1, pred_w2, pred_b2, cur);
        scatter_kernel<<<(NB*NM + 127)/128, 128>>>(start);
    }
    finalize_kernel<<<(NB*NN + 127)/128, 128>>>((float*)d_out);
}

// round 4
// speedup vs baseline: 1.4195x; 1.3589x over previous
#include <cuda_runtime.h>
#include <math_constants.h>

#define NB 4
#define NN 16384
#define NM 512
#define NC 128
#define NK 16
#define NL 6
#define NSTEPS 5

// ---------------- scratch (device globals: no allocations allowed) ----------
__device__ float g_feats[NB*NN*NC];            // encoder output
__device__ float g_Qf[NB*NN*NC];               // feats @ beta^T + b
__device__ float g_Gf[NB*NN*NC];               // feats @ gamma^T + b
__device__ float g_pos4[NB*NN*4];              // padded positions (x,y,z,0)
__device__ float g_wsel[NB*NM*NL*NC];          // selector walks
__device__ float g_rout[2][NB*NM*NL*NC];       // routed walks ping-pong
__device__ float g_disp[NB*NM*3];              // per-step displacements

// ---------------- f32x2 packed helpers --------------------------------------
__device__ __forceinline__ void dfma2(unsigned long long& d,
                                      unsigned long long a,
                                      unsigned long long b) {
    asm("fma.rn.f32x2 %0, %1, %2, %0;" : "+l"(d) : "l"(a), "l"(b));
}
__device__ __forceinline__ unsigned long long packdup(float w) {
    unsigned long long r;
    asm("mov.b64 %0, {%1, %1};" : "=l"(r) : "f"(w));
    return r;
}
__device__ __forceinline__ void unpack2(unsigned long long a, float& lo, float& hi) {
    asm("mov.b64 {%0, %1}, %2;" : "=f"(lo), "=f"(hi) : "l"(a));
}

// ---------------- init: padded positions from xyz ---------------------------
__global__ void init_pos_kernel(const float* __restrict__ xyz) {
    int i = blockIdx.x * blockDim.x + threadIdx.x;
    if (i < NB*NN) {
        float x = xyz[i*3+0], y = xyz[i*3+1], z = xyz[i*3+2];
        float4 v = make_float4(x, y, z, 0.f);
        *(float4*)&g_pos4[(size_t)i*4] = v;
    }
}

// ---------------- encoder: feats = relu(xyz@W1^T+b1)@W2^T+b2 ---------------
__global__ void encode_kernel(const float* __restrict__ xyz,
                              const float* __restrict__ w1, const float* __restrict__ b1,
                              const float* __restrict__ w2, const float* __restrict__ b2) {
    __shared__ float h[4][64];
    int tid = threadIdx.x;              // 128 threads
    int p0 = blockIdx.x * 4;            // 4 points / block
    for (int i = tid; i < 4*64; i += 128) {
        int pt = i >> 6, j = i & 63;
        const float* x = xyz + (size_t)(p0 + pt) * 3;
        float v = b1[j] + w1[j*3+0]*x[0] + w1[j*3+1]*x[1] + w1[j*3+2]*x[2];
        h[pt][j] = fmaxf(v, 0.f);
    }
    __syncthreads();
    float acc[4];
    #pragma unroll
    for (int p = 0; p < 4; p++) acc[p] = b2[tid];
    const float4* wr = (const float4*)(w2 + (size_t)tid * 64);
    #pragma unroll
    for (int j4 = 0; j4 < 16; j4++) {
        float4 w = wr[j4];
        #pragma unroll
        for (int p = 0; p < 4; p++) {
            float4 hv = *(const float4*)&h[p][4*j4];
            acc[p] += w.x*hv.x + w.y*hv.y + w.z*hv.z + w.w*hv.w;
        }
    }
    #pragma unroll
    for (int p = 0; p < 4; p++)
        g_feats[(size_t)(p0 + p) * NC + tid] = acc[p];
}

// ---------------- beta/gamma projections (precomputed once) ----------------
__global__ void proj_kernel(const float* __restrict__ bw, const float* __restrict__ bb,
                            const float* __restrict__ gw, const float* __restrict__ gb) {
    __shared__ float sf[16][128];
    int c = threadIdx.x;                       // 128 threads
    size_t base = (size_t)blockIdx.x * 16 * 128;
    for (int i = c; i < 16*128; i += 128) sf[i>>7][i&127] = g_feats[base + i];
    __syncthreads();
    float accQ[16], accG[16];
    float biasQ = bb[c], biasG = gb[c];
    #pragma unroll
    for (int p = 0; p < 16; p++) { accQ[p] = biasQ; accG[p] = biasG; }
    const float4* wq = (const float4*)(bw + (size_t)c * 128);
    const float4* wg = (const float4*)(gw + (size_t)c * 128);
    for (int j4 = 0; j4 < 32; j4++) {
        float4 a = wq[j4];
        float4 g = wg[j4];
        #pragma unroll
        for (int p = 0; p < 16; p++) {
            float4 f = *(const float4*)&sf[p][4*j4];
            accQ[p] += a.x*f.x + a.y*f.y + a.z*f.z + a.w*f.w;
            accG[p] += g.x*f.x + g.y*f.y + g.z*f.z + g.w*f.w;
        }
    }
    #pragma unroll
    for (int p = 0; p < 16; p++) {
        g_Qf[base + (size_t)p*128 + c] = accQ[p];
        g_Gf[base + (size_t)p*128 + c] = accG[p];
    }
}

// ---------------- fused per-step selector: walkinit + 5 KNN levels ---------
// Grid 256 x 256 threads. Each block owns 8 queries of one batch (1 query per
// warp) and runs all NL-1 selector levels internally, streaming candidate
// positions through 32KB smem tiles. Warp-distributed sorted top-17 list
// (lanes 0..16); parallel insert via ballot/popc/shfl_up. tau (17th-best
// filter) is refreshed once per ballot batch — stale tau only causes no-op
// inserts, never wrong results.
#define KQ 8
#define KTPB 256
#define KTILE 2048

__global__ __launch_bounds__(KTPB, 4)
void knn_step_kernel(const int* __restrict__ start,
                     const float* __restrict__ gumbel, int t) {
    __shared__ float4 stile[KTILE];
    __shared__ int sknn[KQ][NK];
    const int bpb = NM / KQ;                   // 64 blocks per batch
    int b  = blockIdx.x / bpb;
    int warp = threadIdx.x >> 5, lane = threadIdx.x & 31;
    int m = (blockIdx.x % bpb) * KQ + warp;
    int gw = b*NM + m;
    int qidx = start[gw];
    const float4* pos = (const float4*)(g_pos4 + (size_t)b * NN * 4);
    const float* G = g_Gf + (size_t)b*NN*NC;

    // walk[0] = feats[start]
    {
        const float* fr = g_feats + ((size_t)b*NN + qidx) * NC;
        float* wr = g_wsel + (size_t)gw * NL * NC;
        #pragma unroll
        for (int r = 0; r < 4; r++) wr[lane + 32*r] = fr[lane + 32*r];
    }

    for (int l = 0; l < NL-1; l++) {
        float4 qp = pos[qidx];
        float qx = qp.x, qy = qp.y, qz = qp.z;
        float ld = CUDART_INF_F;
        int   li = 0x7FFFFFFF;
        float tau = CUDART_INF_F;

        for (int tb = 0; tb < NN/KTILE; tb++) {
            __syncthreads();
            const float4* src = pos + tb*KTILE;
            for (int i = threadIdx.x; i < KTILE; i += KTPB) stile[i] = src[i];
            __syncthreads();
            int base = tb * KTILE;
            for (int j = lane; j < KTILE; j += 32) {
                float4 p = stile[j];
                float dx = p.x - qx, dy = p.y - qy, dz = p.z - qz;
                float d = fmaf(dz, dz, fmaf(dy, dy, dx*dx));
                int ci = base + j;
                unsigned bal = __ballot_sync(0xffffffffu, d < tau);
                if (bal) {
                    do {
                        int src2 = __ffs(bal) - 1; bal &= bal - 1;
                        float dc = __shfl_sync(0xffffffffu, d, src2);
                        int   ic = __shfl_sync(0xffffffffu, ci, src2);
                        float pd = __shfl_up_sync(0xffffffffu, ld, 1);
                        int   pi = __shfl_up_sync(0xffffffffu, li, 1);
                        unsigned lt = __ballot_sync(0xffffffffu,
                                (ld < dc) || ((ld == dc) && (li < ic))) & 0x1FFFFu;
                        int pn = __popc(lt);
                        if (lane < 17) {
                            if (lane == pn)      { ld = dc; li = ic; }
                            else if (lane > pn)  { ld = pd; li = pi; }
                        }
                    } while (bal);
                    tau = __shfl_sync(0xffffffffu, ld, 16);
                }
            }
        }
        // lane 0 = self. neighbors = lanes 1..16 ascending (d, idx).
        if (lane >= 1 && lane < 17) sknn[warp][lane - 1] = li;
        __syncwarp();

        // logits + gumbel argmax
        const float* Q = g_Qf + ((size_t)b*NN + qidx) * NC;
        float qv0 = Q[lane], qv1 = Q[lane+32], qv2 = Q[lane+64], qv3 = Q[lane+96];
        float pk[16];
        #pragma unroll
        for (int k = 0; k < 16; k++) {
            const float* gr = G + (size_t)sknn[warp][k] * NC;
            pk[k] = qv0*gr[lane] + qv1*gr[lane+32] + qv2*gr[lane+64] + qv3*gr[lane+96];
        }
        #pragma unroll
        for (int k = 0; k < 16; k++) {
            #pragma unroll
            for (int off = 16; off; off >>= 1)
                pk[k] += __shfl_xor_sync(0xffffffffu, pk[k], off);
        }
        const float* gm = gumbel + ((((size_t)t*(NL-1) + l)*NB + b)*NM + m) * NK;
        float best = -CUDART_INF_F; int bk = 0;
        #pragma unroll
        for (int k = 0; k < 16; k++) {
            float s = pk[k] / 11.313708498984761f + gm[k];   // /sqrt(128)
            if (s > best) { best = s; bk = k; }
        }
        qidx = sknn[warp][bk];
        const float* fr = g_feats + ((size_t)b*NN + qidx) * NC;
        float* wr = g_wsel + ((size_t)gw * NL + (l + 1)) * NC;
        #pragma unroll
        for (int r = 0; r < 4; r++) wr[lane + 32*r] = fr[lane + 32*r];
    }
}

// ---------------- route + predict fused ------------------------------------
// Stage buffers hold TWO sequences interleaved: buf[l][channel][s]; matmul
// inner loop runs on fma.rn.f32x2. After the router MLP, the block computes
// the displacement head for its own 2 sequences (predict fused).
__device__ __forceinline__ void mm128i(const float (*in)[128][2],
                                       const float* __restrict__ W,
                                       const float* __restrict__ bias,
                                       float (*out)[128][2],
                                       int tid, bool doRelu) {
    unsigned long long acc[6];
    unsigned long long bb = packdup(bias[tid]);
    #pragma unroll
    for (int i = 0; i < 6; i++) acc[i] = bb;
    const float4* wr = (const float4*)(W + (size_t)tid * 128);
    const unsigned long long* inu = (const unsigned long long*)in;
    for (int j4 = 0; j4 < 32; j4++) {
        float4 w = __ldg(&wr[j4]);
        unsigned long long w0 = packdup(w.x), w1 = packdup(w.y);
        unsigned long long w2 = packdup(w.z), w3 = packdup(w.w);
        #pragma unroll
        for (int l2 = 0; l2 < 6; l2++) {
            const unsigned long long* row = inu + l2*128 + 4*j4;
            dfma2(acc[l2], row[0], w0);
            dfma2(acc[l2], row[1], w1);
            dfma2(acc[l2], row[2], w2);
            dfma2(acc[l2], row[3], w3);
        }
    }
    #pragma unroll
    for (int l2 = 0; l2 < 6; l2++) {
        float v0, v1;
        unpack2(acc[l2], v0, v1);
        if (doRelu) { v0 = fmaxf(v0, 0.f); v1 = fmaxf(v1, 0.f); }
        out[l2][tid][0] = v0;
        out[l2][tid][1] = v1;
    }
}

__global__ void route_kernel(const float* __restrict__ w_in, const float* __restrict__ b_in,
                             const float* __restrict__ w_out, const float* __restrict__ b_out,
                             const float* __restrict__ rt_w1, const float* __restrict__ rt_b1,
                             const float* __restrict__ rt_w2, const float* __restrict__ rt_b2,
                             const float* __restrict__ pw1, const float* __restrict__ pb1,
                             const float* __restrict__ pw2, const float* __restrict__ pb2,
                             int curBuf, int prevBuf) {
    __shared__ __align__(16) float xin[6][128][2];  // curr, reused as attn out
    __shared__ __align__(16) float pin[6][128][2];  // prev, reused as o1
    __shared__ __align__(16) float qs[6][128][2];   // q, reused as r1, then x
    __shared__ __align__(16) float ks[6][128][2];   // k, reused as final
    __shared__ __align__(16) float vs[6][128][2];   // v, reused as h
    __shared__ float sc[2][4][6][6];
    int tid = threadIdx.x;
    size_t seq0 = (size_t)blockIdx.x * 2;
    const float* curr = g_wsel;
    const float* prev = (prevBuf < 0) ? g_wsel : g_rout[prevBuf];
    for (int i = tid; i < 2*6*128; i += 128) {
        int s = i / 768, r = i % 768;          // r = l*128 + c
        ((float*)xin)[r*2 + s] = curr[(seq0 + s)*768 + r];
        ((float*)pin)[r*2 + s] = prev[(seq0 + s)*768 + r];
    }
    __syncthreads();
    mm128i(xin, w_in,            b_in,        qs, tid, false);   // wq
    mm128i(pin, w_in + 128*128,  b_in + 128,  ks, tid, false);   // wk
    mm128i(pin, w_in + 256*128,  b_in + 256,  vs, tid, false);   // wv
    __syncthreads();
    // attention: 8 (s,h) pairs, one warp per pair (x2 sequentially)
    int warp = tid >> 5, lane = tid & 31;
    for (int pp = warp; pp < 8; pp += 4) {
        int s = pp >> 2, h = pp & 3;
        for (int e = lane; e < 36; e += 32) {
            int lq = e / 6, lk = e % 6;
            float d = 0.f;
            #pragma unroll
            for (int dd = 0; dd < 32; dd++)
                d += qs[lq][h*32 + dd][s] * ks[lk][h*32 + dd][s];
            sc[s][h][lq][lk] = d / 5.656854249492381f;   // /sqrt(32)
        }
        __syncwarp();
        if (lane < 6) {
            float mx = -CUDART_INF_F;
            #pragma unroll
            for (int j = 0; j < 6; j++) mx = fmaxf(mx, sc[s][h][lane][j]);
            float ex[6]; float sum = 0.f;
            #pragma unroll
            for (int j = 0; j < 6; j++) { ex[j] = expf(sc[s][h][lane][j] - mx); sum += ex[j]; }
            #pragma unroll
            for (int j = 0; j < 6; j++) sc[s][h][lane][j] = ex[j] / sum;
        }
        __syncwarp();
        for (int lq = 0; lq < 6; lq++) {
            float o = 0.f;
            #pragma unroll
            for (int j = 0; j < 6; j++) o += sc[s][h][lq][j] * vs[j][h*32 + lane][s];
            xin[lq][h*32 + lane][s] = o;   // attn out -> xin
        }
    }
    __syncthreads();
    mm128i(xin, w_out, b_out, pin, tid, false);   // o1
    __syncthreads();
    mm128i(pin, rt_w1, rt_b1, qs, tid, true);     // r1 = relu
    __syncthreads();
    mm128i(qs, rt_w2, rt_b2, ks, tid, false);     // final -> ks
    __syncthreads();
    float* dst = g_rout[curBuf] + seq0*768;
    for (int i = tid; i < 2*6*128; i += 128) {
        int s = i / 768, r = i % 768;
        dst[(size_t)s*768 + r] = ((float*)ks)[r*2 + s];
    }
    // ---- fused predict head for the block's 2 sequences ----
    float* xv = (float*)qs;    // x: [2][256]
    float* hv = (float*)vs;    // h: [2][64]
    {
        int c = tid;
        #pragma unroll
        for (int s = 0; s < 2; s++) {
            float cent = ks[0][c][s];
            float sum = 0.f;
            #pragma unroll
            for (int l2 = 1; l2 < 6; l2++) sum += (ks[l2][c][s] - cent);
            xv[s*256 + c]       = sum * (1.0f / 5.0f);
            xv[s*256 + 128 + c] = cent;
        }
    }
    __syncthreads();
    {
        int s = tid >> 6, j = tid & 63;
        float acc = pb1[j];
        const float4* wr = (const float4*)(pw1 + (size_t)j * 256);
        const float4* xr = (const float4*)(xv + s*256);
        #pragma unroll 8
        for (int j4 = 0; j4 < 64; j4++) {
            float4 wv = wr[j4];
            float4 x4 = xr[j4];
            acc += wv.x*x4.x + wv.y*x4.y + wv.z*x4.z + wv.w*x4.w;
        }
        hv[s*64 + j] = fmaxf(acc, 0.f);
    }
    __syncthreads();
    if (tid < 6) {
        int s = tid / 3, o = tid % 3;
        float acc = pb2[o];
        const float* wr = pw2 + o * 64;
        const float* hh = hv + s*64;
        #pragma unroll 8
        for (int j = 0; j < 64; j++) acc += wr[j] * hh[j];
        g_disp[(seq0 + s)*3 + o] = tanhf(acc);
    }
}

// ---------------- deterministic duplicate-aware scatter-add ----------------
__global__ void scatter_kernel(const int* __restrict__ start) {
    int gid = blockIdx.x * blockDim.x + threadIdx.x;
    if (gid >= NB*NM) return;
    int b = gid >> 9, m = gid & 511;
    int n = start[gid];
    const int* sb = start + b * NM;
    for (int j = 0; j < m; j++) if (sb[j] == n) return;   // not the first owner
    float sx = 0.f, sy = 0.f, sz = 0.f;
    for (int j = m; j < NM; j++) {
        if (sb[j] == n) {
            const float* d = g_disp + (size_t)(b*NM + j) * 3;
            sx += d[0]; sy += d[1]; sz += d[2];
        }
    }
    float* p = g_pos4 + ((size_t)b*NN + n) * 4;
    p[0] += sx; p[1] += sy; p[2] += sz;
}

// ---------------- finalize: padded positions -> output ---------------------
__global__ void finalize_kernel(float* __restrict__ out) {
    int i = blockIdx.x * blockDim.x + threadIdx.x;
    if (i < NB*NN) {
        out[i*3+0] = g_pos4[(size_t)i*4+0];
        out[i*3+1] = g_pos4[(size_t)i*4+1];
        out[i*3+2] = g_pos4[(size_t)i*4+2];
    }
}

// ---------------- host driver ----------------------------------------------
extern "C" void kernel_launch(void* const* d_in, const int* in_sizes, int n_in,
                              void* d_out, int out_size) {
    (void)in_sizes; (void)n_in; (void)out_size;
    const float* xyz      = (const float*)d_in[0];
    const int*   start    = (const int*)  d_in[1];
    const float* gumbel   = (const float*)d_in[2];
    const float* enc_w1   = (const float*)d_in[3];
    const float* enc_b1   = (const float*)d_in[4];
    const float* enc_w2   = (const float*)d_in[5];
    const float* enc_b2   = (const float*)d_in[6];
    const float* beta_w   = (const float*)d_in[7];
    const float* beta_b   = (const float*)d_in[8];
    const float* gamma_w  = (const float*)d_in[9];
    const float* gamma_b  = (const float*)d_in[10];
    const float* attn_w_in  = (const float*)d_in[11];
    const float* attn_b_in  = (const float*)d_in[12];
    const float* attn_w_out = (const float*)d_in[13];
    const float* attn_b_out = (const float*)d_in[14];
    const float* rt_w1    = (const float*)d_in[15];
    const float* rt_b1    = (const float*)d_in[16];
    const float* rt_w2    = (const float*)d_in[17];
    const float* rt_b2    = (const float*)d_in[18];
    const float* pred_w1  = (const float*)d_in[19];
    const float* pred_b1  = (const float*)d_in[20];
    const float* pred_w2  = (const float*)d_in[21];
    const float* pred_b2  = (const float*)d_in[22];

    init_pos_kernel<<<(NB*NN + 127)/128, 128>>>(xyz);
    encode_kernel<<<NB*NN/4, 128>>>(xyz, enc_w1, enc_b1, enc_w2, enc_b2);
    proj_kernel<<<NB*NN/16, 128>>>(beta_w, beta_b, gamma_w, gamma_b);

    for (int t = 0; t < NSTEPS; t++) {
        int cur = t & 1;
        int prv = (t == 0) ? -1 : (1 - cur);
        knn_step_kernel<<<NB*NM/KQ, KTPB>>>(start, gumbel, t);
        route_kernel<<<NB*NM/2, 128>>>(attn_w_in, attn_b_in, attn_w_out, attn_b_out,
                                       rt_w1, rt_b1, rt_w2, rt_b2,
                                       pred_w1, pred_b1, pred_w2, pred_b2, cur, prv);
        scatter_kernel<<<(NB*NM + 127)/128, 128>>>(start);
    }
    finalize_kernel<<<(NB*NN + 127)/128, 128>>>((float*)d_out);
}